// round 4
// baseline (speedup 1.0000x reference)
#include <cuda_runtime.h>
#include <math.h>

constexpr int NB = 128, NA = 2, NH = 128, NW = 128;
constexpr int PLANE = NH * NW;
constexpr float THRESH = 0.6f;
constexpr float OBJ_SCALE = 5.0f;
constexpr float LN_MARGIN = 0.55961579f;   // ln(1.75) > ln(5/3) safety margin
constexpr int NBLOCKS = 4096;              // 1,048,576 threads * 4 cells

// Persistent accumulators (zero at load; reset by last block each run)
__device__ double g_conf2 = 0.0;
__device__ unsigned long long g_cnt = 0ull;
__device__ float  g_sel = 0.0f;
__device__ unsigned g_done = 0u;

__device__ __forceinline__ float sig_precise(float x) { return 1.0f / (1.0f + expf(-x)); }
__device__ __forceinline__ float sig_fast(float x) {
    return __fdividef(1.0f, 1.0f + __expf(-x));
}

__global__ void __launch_bounds__(256) k_fused(const float* __restrict__ out,
                                               const float* __restrict__ tgt,
                                               const float* __restrict__ anc,
                                               float* __restrict__ res) {
    int tid = blockIdx.x * 256 + threadIdx.x;
    int i4 = (tid & 31) * 4;          // 4 consecutive columns
    int r  = tid >> 5;
    int j  = r & 127; r >>= 7;        // row
    int a  = r & 1;                   // anchor (constant per block)
    int b  = r >> 1;                  // batch  (constant per block)

    // ---- issue all 5 plane loads up-front (MLP=5, front-batched) ----
    size_t base = ((size_t)(b * 10 + a * 5) * NH + j) * NW + i4;
    float4 vx = *(const float4*)(out + base);
    float4 vy = *(const float4*)(out + base + 1 * (size_t)PLANE);
    float4 vw = *(const float4*)(out + base + 2 * (size_t)PLANE);
    float4 vh = *(const float4*)(out + base + 3 * (size_t)PLANE);
    float4 vc = *(const float4*)(out + base + 4 * (size_t)PLANE);

    // ---- per-batch constants computed once per block (overlaps loads) ----
    __shared__ float s_gxm, s_gxM, s_gym, s_gyM, s_gw, s_gh, s_garea;
    __shared__ float s_lo, s_hi;
    __shared__ float s_tx, s_ty, s_tw, s_th, s_scl;
    __shared__ float s_aw, s_ah;
    __shared__ int   s_excl;
    if (threadIdx.x == 0) {
        float t0 = tgt[b*4+0], t1 = tgt[b*4+1], t2 = tgt[b*4+2], t3 = tgt[b*4+3];
        float gx = t0 * (float)NW, gy = t1 * (float)NH;
        float gw = t2 * (float)NW, gh = t3 * (float)NH;
        float a0w = anc[0], a0h = anc[1], a1w = anc[2], a1h = anc[3];

        float ga = gw * gh;
        float i0 = fminf(gw, a0w) * fminf(gh, a0h);
        float u0 = ga + 1e-16f + a0w * a0h - i0;
        float i1 = fminf(gw, a1w) * fminf(gh, a1h);
        float u1 = ga + 1e-16f + a1w * a1h - i1;
        int best = (i1 / u1) > (i0 / u0) ? 1 : 0;

        s_gxm = gx - gw * 0.5f; s_gxM = gx + gw * 0.5f;
        s_gym = gy - gh * 0.5f; s_gyM = gy + gh * 0.5f;
        s_gw = gw; s_gh = gh; s_garea = ga;
        s_excl = best * PLANE + (int)gy * NW + (int)gx;

        float aw = a ? a1w : a0w;
        float ah = a ? a1h : a0h;
        s_aw = aw; s_ah = ah;
        float c = logf(ga / (aw * ah));
        s_lo = c - LN_MARGIN; s_hi = c + LN_MARGIN;

        float bw = best ? a1w : a0w;
        float bh = best ? a1h : a0h;
        s_tx = gx - floorf(gx); s_ty = gy - floorf(gy);
        s_tw = logf(gw / bw + 1e-16f); s_th = logf(gh / bh + 1e-16f);
        s_scl = 2.0f - t2 * t3;
    }
    __syncthreads();

    float px4[4] = {vx.x, vx.y, vx.z, vx.w};
    float py4[4] = {vy.x, vy.y, vy.z, vy.w};
    float pw4[4] = {vw.x, vw.y, vw.z, vw.w};
    float ph4[4] = {vh.x, vh.y, vh.z, vh.w};
    float pc4[4] = {vc.x, vc.y, vc.z, vc.w};

    float lo = s_lo, hi = s_hi;
    int   lbase = a * PLANE + j * NW + i4;
    int   kx    = s_excl - lbase;          // in [0,3] iff this thread owns it
    float aw = s_aw, ah = s_ah;
    float gxm = s_gxm, gxM = s_gxM, gym = s_gym, gyM = s_gyM;
    float gw = s_gw, gh = s_gh, garea = s_garea;

    float conf2f = 0.0f;
    float selv = 0.0f;
    int cnt = 0;

    #pragma unroll
    for (int k = 0; k < 4; k++) {       // all indices compile-time after unroll
        bool noobj = true;
        float s = pw4[k] + ph4[k];
        bool is_excl = (k == kx);
        if (((s > lo) && (s < hi)) || is_excl) {
            // slow path: real IoU (math only; data already in registers)
            float px = sig_fast(px4[k]) + (float)(i4 + k);
            float py = sig_fast(py4[k]) + (float)j;
            float pw = __expf(pw4[k]) * aw;
            float ph = __expf(ph4[k]) * ah;
            float mx = fminf(px - pw * 0.5f, gxm);
            float Mx = fmaxf(px + pw * 0.5f, gxM);
            float my = fminf(py - ph * 0.5f, gym);
            float My = fmaxf(py + ph * 0.5f, gyM);
            float cw = pw + gw - (Mx - mx);
            float ch = ph + gh - (My - my);
            float carea = cw * ch;
            float uarea = pw * ph + garea - carea;
            noobj = (cw <= 0.0f) || (ch <= 0.0f) || (carea <= THRESH * uarea);
            if (is_excl) {
                noobj = false;
                float xs = sig_precise(px4[k]);
                float ys = sig_precise(py4[k]);
                float cs = sig_precise(pc4[k]);
                float sc = s_scl;
                float dx = (xs - s_tx) * sc, dy = (ys - s_ty) * sc;
                float dw = (pw4[k] - s_tw) * sc, dh = (ph4[k] - s_th) * sc;
                selv = (dx*dx + dy*dy + dw*dw + dh*dh
                     + OBJ_SCALE * (cs - 1.0f) * (cs - 1.0f)) * (1.0f / (float)NB);
            }
        }
        if (noobj) {
            float rr = sig_fast(pc4[k]);
            conf2f += rr * rr;
            cnt++;
        }
    }

    // ---- block reduce (conf2, cnt, selv) ----
    #pragma unroll
    for (int o = 16; o > 0; o >>= 1) {
        conf2f += __shfl_down_sync(0xffffffffu, conf2f, o);
        cnt    += __shfl_down_sync(0xffffffffu, cnt, o);
        selv   += __shfl_down_sync(0xffffffffu, selv, o);
    }
    __shared__ double sh_c2[8];
    __shared__ int    sh_ct[8];
    __shared__ float  sh_sv[8];
    int lane = threadIdx.x & 31, wrp = threadIdx.x >> 5;
    if (lane == 0) { sh_c2[wrp] = (double)conf2f; sh_ct[wrp] = cnt; sh_sv[wrp] = selv; }
    __syncthreads();
    if (wrp == 0) {
        double c2 = (lane < 8) ? sh_c2[lane] : 0.0;
        int    ct = (lane < 8) ? sh_ct[lane] : 0;
        float  sv = (lane < 8) ? sh_sv[lane] : 0.0f;
        #pragma unroll
        for (int o = 4; o > 0; o >>= 1) {
            c2 += __shfl_down_sync(0xffffffffu, c2, o);
            ct += __shfl_down_sync(0xffffffffu, ct, o);
            sv += __shfl_down_sync(0xffffffffu, sv, o);
        }
        if (lane == 0) {
            atomicAdd(&g_conf2, c2);
            atomicAdd(&g_cnt, (unsigned long long)ct);
            if (sv != 0.0f) atomicAdd(&g_sel, sv);
            __threadfence();
            unsigned old = atomicAdd(&g_done, 1u);
            if (old == (unsigned)(NBLOCKS - 1)) {
                __threadfence();
                res[0] = g_sel + (float)(g_conf2 / (double)g_cnt);
                g_conf2 = 0.0; g_cnt = 0ull; g_sel = 0.0f; g_done = 0u;
            }
        }
    }
}

extern "C" void kernel_launch(void* const* d_in, const int* in_sizes, int n_in,
                              void* d_out, int out_size) {
    const float* out = (const float*)d_in[0];   // (128, 10, 128, 128)
    const float* tgt = (const float*)d_in[1];   // (128, 4)
    const float* anc = (const float*)d_in[2];   // (2, 2)
    float* res = (float*)d_out;

    k_fused<<<NBLOCKS, 256>>>(out, tgt, anc, res);
}